// round 1
// baseline (speedup 1.0000x reference)
#include <cuda_runtime.h>
#include <math.h>

#define NLAT  128
#define NLON  256
#define LMAX  50
#define MMAX  50
#define BATCH 2
#define NPTS  2048
#define MGRID (NLAT*NLON)

// Scratch (allocation-free rule: __device__ globals)
__device__ float4 g_pack[BATCH*NPTS];           // phi, theta-pi, s2, rho
__device__ float  g_W[MMAX][LMAX][NLAT];        // legendre * cc-weights
__device__ float  g_f[BATCH][NLAT][NLON];       // interpolated grid
__device__ float  g_Fre[BATCH][MMAX][NLAT];     // Re(rfft) per (b, m, lat)

// ---------------------------------------------------------------------------
// Kernel 1: cartesian -> spherical features
// ---------------------------------------------------------------------------
__global__ void k_sph(const float* __restrict__ tgt) {
    int i = blockIdx.x * blockDim.x + threadIdx.x;
    if (i >= BATCH * NPTS) return;
    float x = tgt[3*i + 0];
    float y = tgt[3*i + 1];
    float z = tgt[3*i + 2];
    float rho = sqrtf(x*x + y*y + z*z);
    float phi = atan2f(y, x);
    float th  = acosf(z / rho) - (float)M_PI;
    float s2  = phi*phi + th*th;
    g_pack[i] = make_float4(phi, th, s2, rho);
}

// ---------------------------------------------------------------------------
// Kernel 2: SHT weights = P_l^m(cos theta_k) * w_k  (fp64, matches numpy ref)
// block = m (50), thread = k (128)
// ---------------------------------------------------------------------------
__global__ void k_weights() {
    int m = blockIdx.x;
    int k = threadIdx.x;
    const double Nq = (double)(NLAT - 1);          // 127
    double theta = M_PI * (double)k / Nq;
    double x = cos(theta), s = sin(theta);

    // Clenshaw-Curtis weight
    double S = 0.0;
    for (int kk = 1; kk <= (NLAT - 1) / 2; kk++) {
        S += (2.0 / (4.0*kk*kk - 1.0)) * cos(2.0 * theta * (double)kk);
    }
    double w = (2.0 / Nq) * (1.0 - S);
    if (k == 0 || k == NLAT - 1) w *= 0.5;

    // P_m^m via downward phase recurrence
    double pmm = sqrt(1.0 / (4.0 * M_PI));
    for (int mm = 1; mm <= m; mm++)
        pmm = -sqrt((2.0*mm + 1.0) / (2.0*mm)) * s * pmm;

    // zero for l < m
    for (int l = 0; l < m; l++) g_W[m][l][k] = 0.0f;

    g_W[m][m][k] = (float)(pmm * w);
    if (m + 1 < LMAX) {
        double p2 = pmm;
        double p1 = sqrt(2.0*m + 3.0) * x * pmm;
        g_W[m][m+1][k] = (float)(p1 * w);
        for (int l = m + 2; l < LMAX; l++) {
            double ld = (double)l, md = (double)m;
            double a  = sqrt((4.0*ld*ld - 1.0) / (ld*ld - md*md));
            double bb = sqrt(((ld-1.0)*(ld-1.0) - md*md) / (4.0*(ld-1.0)*(ld-1.0) - 1.0));
            double p  = a * (x * p1 - bb * p2);
            g_W[m][l][k] = (float)(p * w);
            p2 = p1; p1 = p;
        }
    }
}

// ---------------------------------------------------------------------------
// Kernel 3: 3-NN search + proportional-distance interpolation
// grid: (MGRID/256, BATCH), 256 threads, targets in SMEM (broadcast loop)
// ---------------------------------------------------------------------------
__global__ void k_nn() {
    __shared__ float4 sp[NPTS];                    // 32 KB
    int b   = blockIdx.y;
    int tid = threadIdx.x;
    const float4* src = &g_pack[b * NPTS];
    for (int j = tid; j < NPTS; j += blockDim.x) sp[j] = src[j];
    __syncthreads();

    int mI   = blockIdx.x * blockDim.x + tid;      // grid point index
    int ilat = mI >> 8;                            // / NLON
    int jlon = mI & (NLON - 1);
    float gx = (float)ilat * ((float)M_PI / (float)NLAT);
    float gy = (float)(jlon - NLAT) * ((float)M_PI / (float)NLAT);
    float g2 = gx*gx + gy*gy;
    float gx2 = 2.0f * gx, gy2 = 2.0f * gy;

    float b0 = 3.4e38f, b1 = 3.4e38f, b2 = 3.4e38f;
    int   i0 = 0, i1 = 0, i2 = 0;

    for (int j = 0; j < NPTS; j++) {
        float4 s  = sp[j];
        float  cr = fmaf(gx2, s.x, gy2 * s.y);     // 2*(gx*phi + gy*th)
        float  d2 = (s.z + g2) - cr;               // same gram form as reference
        if (d2 < b2) {
            if (d2 < b1) {
                b2 = b1; i2 = i1;
                if (d2 < b0) { b1 = b0; i1 = i0; b0 = d2; i0 = j; }
                else         { b1 = d2; i1 = j; }
            } else { b2 = d2; i2 = j; }
        }
    }

    // distances recomputed in direct form (as the reference does post-top_k)
    float4 p0 = sp[i0], p1 = sp[i1], p2 = sp[i2];
    float dx, dy;
    dx = p0.x - gx; dy = p0.y - gy; float dd0 = sqrtf(dx*dx + dy*dy);
    dx = p1.x - gx; dy = p1.y - gy; float dd1 = sqrtf(dx*dx + dy*dy);
    dx = p2.x - gx; dy = p2.y - gy; float dd2 = sqrtf(dx*dx + dy*dy);
    float sum = dd0 + dd1 + dd2;
    float interp = (p0.w*dd0 + p1.w*dd1 + p2.w*dd2) / sum;

    g_f[b][ilat][jlon] = interp;
}

// ---------------------------------------------------------------------------
// Kernel 4: Re(rfft) over longitude, first MMAX modes, forward normalized
// block = (lat k, batch b), 64 threads (m < 50 active)
// ---------------------------------------------------------------------------
__global__ void k_dft() {
    __shared__ float fr[NLON];
    __shared__ float ctab[NLON];
    int b = blockIdx.y, k = blockIdx.x;
    int t = threadIdx.x;
    for (int j = t; j < NLON; j += blockDim.x) {
        fr[j]   = g_f[b][k][j];
        ctab[j] = cospif((float)j / (float)(NLON/2));  // cos(2*pi*j/NLON)
    }
    __syncthreads();
    if (t < MMAX) {
        float acc = 0.0f;
        #pragma unroll 8
        for (int j = 0; j < NLON; j++) {
            acc = fmaf(fr[j], ctab[(t * j) & (NLON - 1)], acc);
        }
        g_Fre[b][t][k] = acc * (2.0f * (float)M_PI / (float)NLON);
    }
}

// ---------------------------------------------------------------------------
// Kernel 5: Legendre contraction  coeff[b,l,m] = sum_k Fre[b,m,k] * W[m,l,k]
// ---------------------------------------------------------------------------
__global__ void k_coeff(float* __restrict__ out) {
    int idx = blockIdx.x * blockDim.x + threadIdx.x;
    if (idx >= BATCH * LMAX * MMAX) return;
    int m = idx % MMAX;
    int l = (idx / MMAX) % LMAX;
    int b = idx / (MMAX * LMAX);
    const float* Fr = g_Fre[b][m];
    const float* Wp = g_W[m][l];
    float acc = 0.0f;
    #pragma unroll 8
    for (int k = 0; k < NLAT; k++) acc = fmaf(Fr[k], Wp[k], acc);
    out[idx] = acc;
}

// ---------------------------------------------------------------------------
extern "C" void kernel_launch(void* const* d_in, const int* in_sizes, int n_in,
                              void* d_out, int out_size) {
    const float* tgt = (const float*)d_in[0];
    float* out = (float*)d_out;

    k_sph<<<(BATCH * NPTS + 255) / 256, 256>>>(tgt);
    k_weights<<<MMAX, NLAT>>>();
    k_nn<<<dim3(MGRID / 256, BATCH), 256>>>();
    k_dft<<<dim3(NLAT, BATCH), 64>>>();
    k_coeff<<<(BATCH * LMAX * MMAX + 255) / 256, 256>>>(out);
}

// round 2
// speedup vs baseline: 1.3790x; 1.3790x over previous
#include <cuda_runtime.h>
#include <math.h>

#define NLAT  128
#define NLON  256
#define LMAX  50
#define MMAX  50
#define BATCH 2
#define NPTS  2048
#define MGRID (NLAT*NLON)
#define PI_F  3.14159265358979323846f

// bin grid over point domain [-pi,pi] x [-pi,0]
#define BINX 32
#define BINY 16
#define NBIN (BINX*BINY)
#define HX (2.0f*PI_F/(float)BINX)   // pi/16
#define HY (PI_F/(float)BINY)        // pi/16
#define X0 (-PI_F)
#define Y0 (-PI_F)

// Scratch (allocation-free rule: __device__ globals)
__device__ float4 g_pack[BATCH*NPTS];           // phi, theta-pi, s2, rho
__device__ float  g_W[MMAX][LMAX][NLAT];        // legendre * cc-weights
__device__ float  g_f[BATCH][NLAT][NLON];       // interpolated grid
__device__ float  g_Fre[BATCH][MMAX][NLAT];     // Re(rfft) per (b, m, lat)

// ---------------------------------------------------------------------------
// Kernel 1: cartesian -> spherical features
// ---------------------------------------------------------------------------
__global__ void k_sph(const float* __restrict__ tgt) {
    int i = blockIdx.x * blockDim.x + threadIdx.x;
    if (i >= BATCH * NPTS) return;
    float x = tgt[3*i + 0];
    float y = tgt[3*i + 1];
    float z = tgt[3*i + 2];
    float rho = sqrtf(x*x + y*y + z*z);
    float phi = atan2f(y, x);
    float th  = acosf(z / rho) - PI_F;
    float s2  = phi*phi + th*th;
    g_pack[i] = make_float4(phi, th, s2, rho);
}

// ---------------------------------------------------------------------------
// Kernel 2: SHT weights = P_l^m(cos theta_k) * w_k  (fp32 — recurrence is
// stable; sub-1e-38 values cast to 0 in the fp32 reference output anyway)
// block = m (50), thread = k (128)
// ---------------------------------------------------------------------------
__global__ void k_weights() {
    int m = blockIdx.x;
    int k = threadIdx.x;
    const float Nq = (float)(NLAT - 1);            // 127
    float tfrac = (float)k / Nq;                   // theta / pi
    float x = cospif(tfrac);
    float s = sinpif(tfrac);

    // Clenshaw-Curtis weight
    float S = 0.0f;
    for (int kk = 1; kk <= (NLAT - 1) / 2; kk++) {
        float c = cospif(2.0f * tfrac * (float)kk);
        S = fmaf(2.0f / (4.0f*kk*kk - 1.0f), c, S);
    }
    float w = (2.0f / Nq) * (1.0f - S);
    if (k == 0 || k == NLAT - 1) w *= 0.5f;

    // P_m^m
    float pmm = sqrtf(1.0f / (4.0f * PI_F));
    for (int mm = 1; mm <= m; mm++)
        pmm = -sqrtf((2.0f*mm + 1.0f) / (2.0f*mm)) * s * pmm;

    for (int l = 0; l < m; l++) g_W[m][l][k] = 0.0f;

    g_W[m][m][k] = pmm * w;
    if (m + 1 < LMAX) {
        float p2 = pmm;
        float p1 = sqrtf(2.0f*m + 3.0f) * x * pmm;
        g_W[m][m+1][k] = p1 * w;
        for (int l = m + 2; l < LMAX; l++) {
            float ld = (float)l, md = (float)m;
            float a  = sqrtf((4.0f*ld*ld - 1.0f) / (ld*ld - md*md));
            float bb = sqrtf(((ld-1.0f)*(ld-1.0f) - md*md) / (4.0f*(ld-1.0f)*(ld-1.0f) - 1.0f));
            float p  = a * (x * p1 - bb * p2);
            g_W[m][l][k] = p * w;
            p2 = p1; p1 = p;
        }
    }
}

// ---------------------------------------------------------------------------
// Kernel 3: binned 3-NN + proportional-distance interpolation
// grid (MGRID/512, BATCH), 512 threads. Each block builds the bin structure
// in smem (redundantly, cheap), then each thread answers one grid point via
// expanding-ring search.
// ---------------------------------------------------------------------------
__device__ __forceinline__ int bin_of(float px, float py) {
    int bx = (int)floorf((px - X0) * (1.0f/HX));
    int by = (int)floorf((py - Y0) * (1.0f/HY));
    bx = min(max(bx, 0), BINX-1);
    by = min(max(by, 0), BINY-1);
    return by * BINX + bx;
}

__global__ __launch_bounds__(512) void k_nn() {
    __shared__ float4 srt[NPTS];          // 32 KB, bin-sorted points
    __shared__ int s_cnt[NBIN];
    __shared__ int s_start[NBIN];
    __shared__ int s_buf[NBIN];
    __shared__ int s_cur[NBIN];

    int b   = blockIdx.y;
    int tid = threadIdx.x;
    const float4* src = &g_pack[b * NPTS];

    // ---- build bins ----
    if (tid < NBIN) s_cnt[tid] = 0;
    __syncthreads();
    for (int j = tid; j < NPTS; j += 512) {
        float4 p = src[j];
        atomicAdd(&s_cnt[bin_of(p.x, p.y)], 1);
    }
    __syncthreads();
    // Hillis-Steele inclusive scan of s_cnt (NBIN == blockDim == 512)
    s_buf[tid] = s_cnt[tid];
    __syncthreads();
    for (int off = 1; off < NBIN; off <<= 1) {
        int xv = s_buf[tid];
        int yv = (tid >= off) ? s_buf[tid - off] : 0;
        __syncthreads();
        s_buf[tid] = xv + yv;
        __syncthreads();
    }
    s_start[tid] = s_buf[tid] - s_cnt[tid];   // exclusive
    s_cur[tid]   = s_buf[tid] - s_cnt[tid];
    __syncthreads();
    for (int j = tid; j < NPTS; j += 512) {
        float4 p = src[j];
        int pos = atomicAdd(&s_cur[bin_of(p.x, p.y)], 1);
        srt[pos] = p;
    }
    __syncthreads();

    // ---- query ----
    int mI   = blockIdx.x * 512 + tid;
    int ilat = mI >> 8;
    int jlon = mI & (NLON - 1);
    float gx = (float)ilat * (PI_F / (float)NLAT);
    float gy = (float)(jlon - NLAT) * (PI_F / (float)NLAT);
    float g2 = gx*gx + gy*gy;
    float gx2 = 2.0f * gx, gy2 = 2.0f * gy;

    int qbx = min(max((int)floorf((gx - X0) * (1.0f/HX)), 0), BINX-1);
    int qby = min(max((int)floorf((gy - Y0) * (1.0f/HY)), 0), BINY-1);

    float b0 = 3.4e38f, b1 = 3.4e38f, b2 = 3.4e38f;
    int   i0 = 0, i1 = 0, i2 = 0;

    #define SCAN_CELL(cx, cy) {                                           \
        int c = (cy) * BINX + (cx);                                       \
        int s = s_start[c], e = s + s_cnt[c];                             \
        for (int t = s; t < e; t++) {                                     \
            float4 sp = srt[t];                                           \
            float cr = fmaf(gx2, sp.x, gy2 * sp.y);                       \
            float d2 = (sp.z + g2) - cr;                                  \
            if (d2 < b2) {                                                \
                if (d2 < b1) {                                            \
                    b2 = b1; i2 = i1;                                     \
                    if (d2 < b0) { b1 = b0; i1 = i0; b0 = d2; i0 = t; }   \
                    else         { b1 = d2; i1 = t; }                     \
                } else { b2 = d2; i2 = t; }                               \
            }                                                             \
        }                                                                 \
    }

    for (int r = 0; r < BINX + 2; r++) {
        int xl = qbx - r, xr = qbx + r, yl = qby - r, yr = qby + r;
        int cxl = max(xl, 0), cxr = min(xr, BINX-1);
        if (r == 0) {
            SCAN_CELL(qbx, qby);
        } else {
            if (yl >= 0)      for (int x = cxl; x <= cxr; x++) SCAN_CELL(x, yl);
            if (yr <= BINY-1) for (int x = cxl; x <= cxr; x++) SCAN_CELL(x, yr);
            int cyl = max(yl + 1, 0), cyr = min(yr - 1, BINY-1);
            if (xl >= 0)      for (int y = cyl; y <= cyr; y++) SCAN_CELL(xl, y);
            if (xr <= BINX-1) for (int y = cyl; y <= cyr; y++) SCAN_CELL(xr, y);
        }
        bool fullX = (xl <= 0) && (xr >= BINX-1);
        bool fullY = (yl <= 0) && (yr >= BINY-1);
        if (fullX && fullY) break;
        // conservative lower bound on distance to any unsearched cell
        float dlb = 3.4e38f;
        if (xl > 0)        dlb = fminf(dlb, gx - (X0 + (float)xl * HX));
        if (xr < BINX-1)   dlb = fminf(dlb, (X0 + (float)(xr+1) * HX) - gx);
        if (yl > 0)        dlb = fminf(dlb, gy - (Y0 + (float)yl * HY));
        if (yr < BINY-1)   dlb = fminf(dlb, fmaxf(0.0f, (Y0 + (float)(yr+1) * HY) - gy));
        if (b2 < dlb * dlb - 1e-4f) break;
    }
    #undef SCAN_CELL

    float4 p0 = srt[i0], p1 = srt[i1], p2 = srt[i2];
    float dx, dy;
    dx = p0.x - gx; dy = p0.y - gy; float dd0 = sqrtf(dx*dx + dy*dy);
    dx = p1.x - gx; dy = p1.y - gy; float dd1 = sqrtf(dx*dx + dy*dy);
    dx = p2.x - gx; dy = p2.y - gy; float dd2 = sqrtf(dx*dx + dy*dy);
    float sum = dd0 + dd1 + dd2;
    float interp = (p0.w*dd0 + p1.w*dd1 + p2.w*dd2) / sum;

    g_f[b][ilat][jlon] = interp;
}

// ---------------------------------------------------------------------------
// Kernel 4: Re(rfft) over longitude, first MMAX modes, forward normalized
// block = (lat group of 4, batch), 256 threads
// ---------------------------------------------------------------------------
__global__ void k_dft() {
    __shared__ float fr[4][NLON];
    __shared__ float ctab[NLON];
    int b = blockIdx.y, k0 = blockIdx.x * 4;
    int t = threadIdx.x;
    for (int j = t; j < NLON; j += 256)
        ctab[j] = cospif((float)j * (1.0f / 128.0f));  // cos(2*pi*j/256)
    for (int idx = t; idx < 4 * NLON; idx += 256)
        fr[idx >> 8][idx & 255] = g_f[b][k0 + (idx >> 8)][idx & 255];
    __syncthreads();
    int m  = t & 63;
    int rw = t >> 6;
    if (m < MMAX) {
        float acc = 0.0f;
        int idx = 0;
        #pragma unroll 8
        for (int j = 0; j < NLON; j++) {
            acc = fmaf(fr[rw][j], ctab[idx], acc);
            idx = (idx + m) & (NLON - 1);
        }
        g_Fre[b][m][k0 + rw] = acc * (2.0f * PI_F / (float)NLON);
    }
}

// ---------------------------------------------------------------------------
// Kernel 5: Legendre contraction  coeff[b,l,m] = sum_k Fre[b,m,k] * W[m,l,k]
// ---------------------------------------------------------------------------
__global__ void k_coeff(float* __restrict__ out) {
    int idx = blockIdx.x * blockDim.x + threadIdx.x;
    if (idx >= BATCH * LMAX * MMAX) return;
    int m = idx % MMAX;
    int l = (idx / MMAX) % LMAX;
    int b = idx / (MMAX * LMAX);
    const float* Fr = g_Fre[b][m];
    const float* Wp = g_W[m][l];
    float acc = 0.0f;
    #pragma unroll 8
    for (int k = 0; k < NLAT; k++) acc = fmaf(Fr[k], Wp[k], acc);
    out[idx] = acc;
}

// ---------------------------------------------------------------------------
extern "C" void kernel_launch(void* const* d_in, const int* in_sizes, int n_in,
                              void* d_out, int out_size) {
    const float* tgt = (const float*)d_in[0];
    float* out = (float*)d_out;

    k_sph<<<(BATCH * NPTS + 255) / 256, 256>>>(tgt);
    k_weights<<<MMAX, NLAT>>>();
    k_nn<<<dim3(MGRID / 512, BATCH), 512>>>();
    k_dft<<<dim3(NLAT / 4, BATCH), 256>>>();
    k_coeff<<<(BATCH * LMAX * MMAX + 255) / 256, 256>>>(out);
}

// round 3
// speedup vs baseline: 2.7204x; 1.9728x over previous
#include <cuda_runtime.h>
#include <math.h>

#define NLAT  128
#define NLON  256
#define LMAX  50
#define MMAX  50
#define BATCH 2
#define NPTS  2048
#define MGRID (NLAT*NLON)
#define PI_F  3.14159265358979323846f

// bin grid over point domain [-pi,pi] x [-pi,0]
#define BINX 32
#define BINY 16
#define NBIN (BINX*BINY)
#define HX (2.0f*PI_F/(float)BINX)   // pi/16
#define HY (PI_F/(float)BINY)        // pi/16
#define X0 (-PI_F)
#define Y0 (-PI_F)

// Scratch (allocation-free rule: __device__ globals)
__device__ float4 g_pack[BATCH*NPTS];           // phi, theta-pi, s2, rho
__device__ float  g_W[MMAX][LMAX][NLAT];        // legendre * cc-weights
__device__ float  g_f[BATCH][NLAT][NLON];       // interpolated grid
__device__ float  g_Fre[BATCH][MMAX][NLAT];     // Re(rfft) per (b, m, lat)

// ---------------------------------------------------------------------------
// Kernel 1: cartesian -> spherical features
// ---------------------------------------------------------------------------
__global__ void k_sph(const float* __restrict__ tgt) {
    int i = blockIdx.x * blockDim.x + threadIdx.x;
    if (i >= BATCH * NPTS) return;
    float x = tgt[3*i + 0];
    float y = tgt[3*i + 1];
    float z = tgt[3*i + 2];
    float rho = sqrtf(x*x + y*y + z*z);
    float phi = atan2f(y, x);
    float th  = acosf(z / rho) - PI_F;
    float s2  = phi*phi + th*th;
    g_pack[i] = make_float4(phi, th, s2, rho);
}

// ---------------------------------------------------------------------------
// Kernel 2: SHT weights = P_l^m(cos theta_k) * w_k  (fp32)
// ---------------------------------------------------------------------------
__global__ void k_weights() {
    int m = blockIdx.x;
    int k = threadIdx.x;
    const float Nq = (float)(NLAT - 1);            // 127
    float tfrac = (float)k / Nq;                   // theta / pi
    float x = cospif(tfrac);
    float s = sinpif(tfrac);

    // Clenshaw-Curtis weight
    float S = 0.0f;
    for (int kk = 1; kk <= (NLAT - 1) / 2; kk++) {
        float c = cospif(2.0f * tfrac * (float)kk);
        S = fmaf(2.0f / (4.0f*kk*kk - 1.0f), c, S);
    }
    float w = (2.0f / Nq) * (1.0f - S);
    if (k == 0 || k == NLAT - 1) w *= 0.5f;

    // P_m^m
    float pmm = sqrtf(1.0f / (4.0f * PI_F));
    for (int mm = 1; mm <= m; mm++)
        pmm = -sqrtf((2.0f*mm + 1.0f) / (2.0f*mm)) * s * pmm;

    for (int l = 0; l < m; l++) g_W[m][l][k] = 0.0f;

    g_W[m][m][k] = pmm * w;
    if (m + 1 < LMAX) {
        float p2 = pmm;
        float p1 = sqrtf(2.0f*m + 3.0f) * x * pmm;
        g_W[m][m+1][k] = p1 * w;
        for (int l = m + 2; l < LMAX; l++) {
            float ld = (float)l, md = (float)m;
            float a  = sqrtf((4.0f*ld*ld - 1.0f) / (ld*ld - md*md));
            float bb = sqrtf(((ld-1.0f)*(ld-1.0f) - md*md) / (4.0f*(ld-1.0f)*(ld-1.0f) - 1.0f));
            float p  = a * (x * p1 - bb * p2);
            g_W[m][l][k] = p * w;
            p2 = p1; p1 = p;
        }
    }
}

// ---------------------------------------------------------------------------
// Kernel 3: binned 3-NN with per-cell rectangle pruning
// ---------------------------------------------------------------------------
__device__ __forceinline__ int bin_of(float px, float py) {
    int bx = (int)floorf((px - X0) * (1.0f/HX));
    int by = (int)floorf((py - Y0) * (1.0f/HY));
    bx = min(max(bx, 0), BINX-1);
    by = min(max(by, 0), BINY-1);
    return by * BINX + bx;
}

__global__ __launch_bounds__(512) void k_nn() {
    __shared__ float4 srt[NPTS];          // 32 KB, bin-sorted points
    __shared__ int s_cnt[NBIN];
    __shared__ int s_start[NBIN];
    __shared__ int s_buf[NBIN];
    __shared__ int s_cur[NBIN];

    int b   = blockIdx.y;
    int tid = threadIdx.x;
    const float4* src = &g_pack[b * NPTS];

    // ---- build bins ----
    if (tid < NBIN) s_cnt[tid] = 0;
    __syncthreads();
    for (int j = tid; j < NPTS; j += 512) {
        float4 p = src[j];
        atomicAdd(&s_cnt[bin_of(p.x, p.y)], 1);
    }
    __syncthreads();
    // Hillis-Steele inclusive scan (NBIN == blockDim == 512)
    s_buf[tid] = s_cnt[tid];
    __syncthreads();
    for (int off = 1; off < NBIN; off <<= 1) {
        int xv = s_buf[tid];
        int yv = (tid >= off) ? s_buf[tid - off] : 0;
        __syncthreads();
        s_buf[tid] = xv + yv;
        __syncthreads();
    }
    s_start[tid] = s_buf[tid] - s_cnt[tid];   // exclusive
    s_cur[tid]   = s_buf[tid] - s_cnt[tid];
    __syncthreads();
    for (int j = tid; j < NPTS; j += 512) {
        float4 p = src[j];
        int pos = atomicAdd(&s_cur[bin_of(p.x, p.y)], 1);
        srt[pos] = p;
    }
    __syncthreads();

    // ---- query ----
    int mI   = blockIdx.x * 512 + tid;
    int ilat = mI >> 8;
    int jlon = mI & (NLON - 1);
    float gx = (float)ilat * (PI_F / (float)NLAT);
    float gy = (float)(jlon - NLAT) * (PI_F / (float)NLAT);
    float g2 = gx*gx + gy*gy;
    float gx2 = 2.0f * gx, gy2 = 2.0f * gy;

    int qbx = min(max((int)floorf((gx - X0) * (1.0f/HX)), 0), BINX-1);
    int qby = min(max((int)floorf((gy - Y0) * (1.0f/HY)), 0), BINY-1);

    float b0 = 3.4e38f, b1 = 3.4e38f, b2 = 3.4e38f;
    int   i0 = 0, i1 = 0, i2 = 0;

    // scan a cell only if (a) non-empty and (b) its rect lower bound beats b2
    #define SCAN_CELL(cx, cy) {                                             \
        int c = (cy) * BINX + (cx);                                         \
        int cnt = s_cnt[c];                                                 \
        if (cnt) {                                                          \
            float rx0 = X0 + (float)(cx) * HX;                              \
            float ry0 = Y0 + (float)(cy) * HY;                              \
            float ddx = fmaxf(fmaxf(rx0 - gx, gx - (rx0 + HX)), 0.0f);      \
            float ddy = fmaxf(fmaxf(ry0 - gy, gy - (ry0 + HY)), 0.0f);      \
            if (fmaf(ddx, ddx, ddy*ddy) < b2 + 1e-4f) {                     \
                int s = s_start[c], e = s + cnt;                            \
                for (int t = s; t < e; t++) {                               \
                    float4 sp = srt[t];                                     \
                    float cr = fmaf(gx2, sp.x, gy2 * sp.y);                 \
                    float d2 = (sp.z + g2) - cr;                            \
                    if (d2 < b2) {                                          \
                        if (d2 < b1) {                                      \
                            b2 = b1; i2 = i1;                               \
                            if (d2 < b0) { b1 = b0; i1 = i0; b0 = d2; i0 = t; } \
                            else         { b1 = d2; i1 = t; }               \
                        } else { b2 = d2; i2 = t; }                         \
                    }                                                       \
                }                                                           \
            }                                                               \
        }                                                                   \
    }

    for (int r = 0; r < BINX + 2; r++) {
        int xl = qbx - r, xr = qbx + r, yl = qby - r, yr = qby + r;
        int cxl = max(xl, 0), cxr = min(xr, BINX-1);
        if (r == 0) {
            SCAN_CELL(qbx, qby);
        } else {
            if (yl >= 0)      for (int x = cxl; x <= cxr; x++) SCAN_CELL(x, yl);
            if (yr <= BINY-1) for (int x = cxl; x <= cxr; x++) SCAN_CELL(x, yr);
            int cyl = max(yl + 1, 0), cyr = min(yr - 1, BINY-1);
            if (xl >= 0)      for (int y = cyl; y <= cyr; y++) SCAN_CELL(xl, y);
            if (xr <= BINX-1) for (int y = cyl; y <= cyr; y++) SCAN_CELL(xr, y);
        }
        bool fullX = (xl <= 0) && (xr >= BINX-1);
        bool fullY = (yl <= 0) && (yr >= BINY-1);
        if (fullX && fullY) break;
        // conservative lower bound on distance to any unsearched cell (slab)
        float dlb = 3.4e38f;
        if (xl > 0)        dlb = fminf(dlb, gx - (X0 + (float)xl * HX));
        if (xr < BINX-1)   dlb = fminf(dlb, (X0 + (float)(xr+1) * HX) - gx);
        if (yl > 0)        dlb = fminf(dlb, gy - (Y0 + (float)yl * HY));
        if (yr < BINY-1)   dlb = fminf(dlb, fmaxf(0.0f, (Y0 + (float)(yr+1) * HY) - gy));
        if (b2 < dlb * dlb - 1e-4f) break;
    }
    #undef SCAN_CELL

    float4 p0 = srt[i0], p1 = srt[i1], p2 = srt[i2];
    float dx, dy;
    dx = p0.x - gx; dy = p0.y - gy; float dd0 = sqrtf(dx*dx + dy*dy);
    dx = p1.x - gx; dy = p1.y - gy; float dd1 = sqrtf(dx*dx + dy*dy);
    dx = p2.x - gx; dy = p2.y - gy; float dd2 = sqrtf(dx*dx + dy*dy);
    float sum = dd0 + dd1 + dd2;
    float interp = (p0.w*dd0 + p1.w*dd1 + p2.w*dd2) / sum;

    g_f[b][ilat][jlon] = interp;
}

// ---------------------------------------------------------------------------
// Kernel 4: Re(rfft) over longitude, first MMAX modes, forward normalized
// block = (2 lat rows, batch), 128 threads
// ---------------------------------------------------------------------------
__global__ void k_dft() {
    __shared__ float fr[2][NLON];
    __shared__ float ctab[NLON];
    int b = blockIdx.y, k0 = blockIdx.x * 2;
    int t = threadIdx.x;
    for (int j = t; j < NLON; j += 128)
        ctab[j] = cospif((float)j * (1.0f / 128.0f));  // cos(2*pi*j/256)
    for (int idx = t; idx < 2 * NLON; idx += 128)
        fr[idx >> 8][idx & 255] = g_f[b][k0 + (idx >> 8)][idx & 255];
    __syncthreads();
    int m  = t & 63;
    int rw = t >> 6;
    if (m < MMAX) {
        float acc = 0.0f;
        int idx = 0;
        #pragma unroll 8
        for (int j = 0; j < NLON; j++) {
            acc = fmaf(fr[rw][j], ctab[idx], acc);
            idx = (idx + m) & (NLON - 1);
        }
        g_Fre[b][m][k0 + rw] = acc * (2.0f * PI_F / (float)NLON);
    }
}

// ---------------------------------------------------------------------------
// Kernel 5: Legendre contraction  coeff[b,l,m] = sum_k Fre[b,m,k] * W[m,l,k]
// ---------------------------------------------------------------------------
__global__ void k_coeff(float* __restrict__ out) {
    int idx = blockIdx.x * blockDim.x + threadIdx.x;
    if (idx >= BATCH * LMAX * MMAX) return;
    int m = idx % MMAX;
    int l = (idx / MMAX) % LMAX;
    int b = idx / (MMAX * LMAX);
    const float* Fr = g_Fre[b][m];
    const float* Wp = g_W[m][l];
    float acc = 0.0f;
    #pragma unroll 8
    for (int k = 0; k < NLAT; k++) acc = fmaf(Fr[k], Wp[k], acc);
    out[idx] = acc;
}

// ---------------------------------------------------------------------------
extern "C" void kernel_launch(void* const* d_in, const int* in_sizes, int n_in,
                              void* d_out, int out_size) {
    const float* tgt = (const float*)d_in[0];
    float* out = (float*)d_out;

    k_sph<<<(BATCH * NPTS + 255) / 256, 256>>>(tgt);
    k_weights<<<MMAX, NLAT>>>();
    k_nn<<<dim3(MGRID / 512, BATCH), 512>>>();
    k_dft<<<dim3(NLAT / 2, BATCH), 128>>>();
    k_coeff<<<(BATCH * LMAX * MMAX + 255) / 256, 256>>>(out);
}

// round 4
// speedup vs baseline: 6.8076x; 2.5024x over previous
#include <cuda_runtime.h>
#include <math.h>

#define NLAT  128
#define NLON  256
#define LMAX  50
#define MMAX  50
#define BATCH 2
#define NPTS  2048
#define MGRID (NLAT*NLON)
#define PI_F  3.14159265358979323846f

// bin grid over point domain [-pi,pi] x [-pi,0]
#define BINX 32
#define BINY 16
#define NBIN (BINX*BINY)
#define HX (2.0f*PI_F/(float)BINX)   // pi/16
#define HY (PI_F/(float)BINY)        // pi/16
#define X0 (-PI_F)
#define Y0 (-PI_F)

// Scratch (allocation-free rule: __device__ globals)
__device__ float4 g_pack[BATCH*NPTS];            // phi, theta-pi, s2, rho
__device__ float  g_W[MMAX][NLAT][LMAX];         // legendre*ccw, k-major
__device__ float  g_ft[BATCH][NLON][NLAT];       // interpolated grid, TRANSPOSED

// ---------------------------------------------------------------------------
// Kernel 1 (fused): blocks [0,16): cart->spherical; blocks [16,66): weights
// ---------------------------------------------------------------------------
__global__ void k_init(const float* __restrict__ tgt) {
    int blk = blockIdx.x;
    int t   = threadIdx.x;
    if (blk < 16) {
        int i = blk * 256 + t;
        float x = tgt[3*i + 0];
        float y = tgt[3*i + 1];
        float z = tgt[3*i + 2];
        float rho = sqrtf(x*x + y*y + z*z);
        float phi = atan2f(y, x);
        float th  = acosf(z / rho) - PI_F;
        float s2  = phi*phi + th*th;
        g_pack[i] = make_float4(phi, th, s2, rho);
        return;
    }
    if (t >= NLAT) return;
    int m = blk - 16;
    int k = t;
    const float Nq = (float)(NLAT - 1);            // 127
    float tfrac = (float)k / Nq;                   // theta / pi
    float x = cospif(tfrac);
    float s = sinpif(tfrac);

    // Clenshaw-Curtis weight
    float S = 0.0f;
    for (int kk = 1; kk <= (NLAT - 1) / 2; kk++) {
        float c = cospif(2.0f * tfrac * (float)kk);
        S = fmaf(2.0f / (4.0f*kk*kk - 1.0f), c, S);
    }
    float w = (2.0f / Nq) * (1.0f - S);
    if (k == 0 || k == NLAT - 1) w *= 0.5f;

    // P_m^m
    float pmm = sqrtf(1.0f / (4.0f * PI_F));
    for (int mm = 1; mm <= m; mm++)
        pmm = -sqrtf((2.0f*mm + 1.0f) / (2.0f*mm)) * s * pmm;

    for (int l = 0; l < m; l++) g_W[m][k][l] = 0.0f;

    g_W[m][k][m] = pmm * w;
    if (m + 1 < LMAX) {
        float p2 = pmm;
        float p1 = sqrtf(2.0f*m + 3.0f) * x * pmm;
        g_W[m][k][m+1] = p1 * w;
        for (int l = m + 2; l < LMAX; l++) {
            float ld = (float)l, md = (float)m;
            float a  = sqrtf((4.0f*ld*ld - 1.0f) / (ld*ld - md*md));
            float bb = sqrtf(((ld-1.0f)*(ld-1.0f) - md*md) / (4.0f*(ld-1.0f)*(ld-1.0f) - 1.0f));
            float p  = a * (x * p1 - bb * p2);
            g_W[m][k][l] = p * w;
            p2 = p1; p1 = p;
        }
    }
}

// ---------------------------------------------------------------------------
// Kernel 2: binned 3-NN with per-cell rect pruning + domain-aware termination
// ---------------------------------------------------------------------------
__device__ __forceinline__ int bin_of(float px, float py) {
    int bx = (int)floorf((px - X0) * (1.0f/HX));
    int by = (int)floorf((py - Y0) * (1.0f/HY));
    bx = min(max(bx, 0), BINX-1);
    by = min(max(by, 0), BINY-1);
    return by * BINX + bx;
}

__global__ __launch_bounds__(512) void k_nn() {
    __shared__ float4 srt[NPTS];          // 32 KB, bin-sorted points
    __shared__ int s_cnt[NBIN];
    __shared__ int s_start[NBIN];
    __shared__ int s_buf[NBIN];
    __shared__ int s_cur[NBIN];

    int b   = blockIdx.y;
    int tid = threadIdx.x;
    const float4* src = &g_pack[b * NPTS];

    // ---- build bins ----
    if (tid < NBIN) s_cnt[tid] = 0;
    __syncthreads();
    for (int j = tid; j < NPTS; j += 512) {
        float4 p = src[j];
        atomicAdd(&s_cnt[bin_of(p.x, p.y)], 1);
    }
    __syncthreads();
    s_buf[tid] = s_cnt[tid];
    __syncthreads();
    for (int off = 1; off < NBIN; off <<= 1) {
        int xv = s_buf[tid];
        int yv = (tid >= off) ? s_buf[tid - off] : 0;
        __syncthreads();
        s_buf[tid] = xv + yv;
        __syncthreads();
    }
    s_start[tid] = s_buf[tid] - s_cnt[tid];
    s_cur[tid]   = s_buf[tid] - s_cnt[tid];
    __syncthreads();
    for (int j = tid; j < NPTS; j += 512) {
        float4 p = src[j];
        int pos = atomicAdd(&s_cur[bin_of(p.x, p.y)], 1);
        srt[pos] = p;
    }
    __syncthreads();

    // ---- query (ilat fast so g_ft write is coalesced) ----
    int mI   = blockIdx.x * 512 + tid;
    int ilat = mI & (NLAT - 1);
    int jlon = mI >> 7;
    float gx = (float)ilat * (PI_F / (float)NLAT);
    float gy = (float)(jlon - NLAT) * (PI_F / (float)NLAT);
    float g2 = gx*gx + gy*gy;
    float gx2 = 2.0f * gx, gy2 = 2.0f * gy;
    float domY = fmaxf(gy, 0.0f);          // query dist to point domain y<=0
    float domY2 = domY * domY;

    int qbx = min(max((int)floorf((gx - X0) * (1.0f/HX)), 0), BINX-1);
    int qby = min(max((int)floorf((gy - Y0) * (1.0f/HY)), 0), BINY-1);

    float b0 = 3.4e38f, b1 = 3.4e38f, b2 = 3.4e38f;
    int   i0 = 0, i1 = 0, i2 = 0;

    #define SCAN_CELL(cx, cy) {                                             \
        int c = (cy) * BINX + (cx);                                         \
        int cnt = s_cnt[c];                                                 \
        if (cnt) {                                                          \
            float rx0 = X0 + (float)(cx) * HX;                              \
            float ry0 = Y0 + (float)(cy) * HY;                              \
            float ddx = fmaxf(fmaxf(rx0 - gx, gx - (rx0 + HX)), 0.0f);      \
            float ddy = fmaxf(fmaxf(ry0 - gy, gy - (ry0 + HY)), 0.0f);      \
            if (fmaf(ddx, ddx, ddy*ddy) < b2 + 1e-4f) {                     \
                int s = s_start[c], e = s + cnt;                            \
                for (int t = s; t < e; t++) {                               \
                    float4 sp = srt[t];                                     \
                    float cr = fmaf(gx2, sp.x, gy2 * sp.y);                 \
                    float d2 = (sp.z + g2) - cr;                            \
                    if (d2 < b2) {                                          \
                        if (d2 < b1) {                                      \
                            b2 = b1; i2 = i1;                               \
                            if (d2 < b0) { b1 = b0; i1 = i0; b0 = d2; i0 = t; } \
                            else         { b1 = d2; i1 = t; }               \
                        } else { b2 = d2; i2 = t; }                         \
                    }                                                       \
                }                                                           \
            }                                                               \
        }                                                                   \
    }

    for (int r = 0; r < BINX + 2; r++) {
        int xl = qbx - r, xr = qbx + r, yl = qby - r, yr = qby + r;
        int cxl = max(xl, 0), cxr = min(xr, BINX-1);
        if (r == 0) {
            SCAN_CELL(qbx, qby);
        } else {
            if (yl >= 0)      for (int x = cxl; x <= cxr; x++) SCAN_CELL(x, yl);
            if (yr <= BINY-1) for (int x = cxl; x <= cxr; x++) SCAN_CELL(x, yr);
            int cyl = max(yl + 1, 0), cyr = min(yr - 1, BINY-1);
            if (xl >= 0)      for (int y = cyl; y <= cyr; y++) SCAN_CELL(xl, y);
            if (xr <= BINX-1) for (int y = cyl; y <= cyr; y++) SCAN_CELL(xr, y);
        }
        bool fullX = (xl <= 0) && (xr >= BINX-1);
        bool fullY = (yl <= 0) && (yr >= BINY-1);
        if (fullX && fullY) break;
        // lower bounds on distance to unsearched cells.
        // x-slab cells also satisfy y in [-pi,0] -> add domY^2.
        float dbx = 3.4e38f, dby = 3.4e38f;
        if (xl > 0)        dbx = fminf(dbx, gx - (X0 + (float)xl * HX));
        if (xr < BINX-1)   dbx = fminf(dbx, (X0 + (float)(xr+1) * HX) - gx);
        if (yl > 0)        dby = fminf(dby, gy - (Y0 + (float)yl * HY));
        if (yr < BINY-1)   dby = fminf(dby, fmaxf(0.0f, (Y0 + (float)(yr+1) * HY) - gy));
        float dlb2 = fminf(fmaf(dbx, dbx, domY2), dby * dby);
        if (b2 < dlb2 - 1e-4f) break;
    }
    #undef SCAN_CELL

    float4 p0 = srt[i0], p1 = srt[i1], p2 = srt[i2];
    float dx, dy;
    dx = p0.x - gx; dy = p0.y - gy; float dd0 = sqrtf(dx*dx + dy*dy);
    dx = p1.x - gx; dy = p1.y - gy; float dd1 = sqrtf(dx*dx + dy*dy);
    dx = p2.x - gx; dy = p2.y - gy; float dd2 = sqrtf(dx*dx + dy*dy);
    float sum = dd0 + dd1 + dd2;
    float interp = (p0.w*dd0 + p1.w*dd1 + p2.w*dd2) / sum;

    g_ft[b][jlon][ilat] = interp;          // transposed, coalesced
}

// ---------------------------------------------------------------------------
// Kernel 3 (fused DFT + Legendre): block = (m, b), 128 threads.
// Phase 1: thread k computes Fre[k] = (2pi/256) * sum_j f[b,k,j] cos(2pi m j/256)
// Phase 2: split-K Legendre contraction from smem W tile -> out[b,l,m]
// ---------------------------------------------------------------------------
__global__ __launch_bounds__(128) void k_sht(float* __restrict__ out) {
    __shared__ float ctab[NLON];
    __shared__ float fre[NLAT];
    __shared__ float sW[NLAT * LMAX];      // 25.6 KB
    __shared__ float ps[2][64];

    int m = blockIdx.x, b = blockIdx.y;
    int t = threadIdx.x;

    // cos table
    ctab[t]       = cospif((float)t * (1.0f / 128.0f));
    ctab[t + 128] = cospif((float)(t + 128) * (1.0f / 128.0f));
    // W tile (coalesced)
    const float* wsrc = &g_W[m][0][0];
    #pragma unroll
    for (int i = 0; i < NLAT * LMAX / 128; i++)
        sW[t + i * 128] = wsrc[t + i * 128];
    __syncthreads();

    // phase 1: DFT over longitude
    const float* fp = &g_ft[b][0][t];      // stride NLAT between j's, coalesced across t
    int m2 = (2 * m) & 255, m3 = (3 * m) & 255, m4 = (4 * m) & 255;
    float a0 = 0.f, a1 = 0.f, a2 = 0.f, a3 = 0.f;
    int idx = 0;
    #pragma unroll 4
    for (int j = 0; j < NLON; j += 4) {
        float f0 = fp[(j + 0) * NLAT];
        float f1 = fp[(j + 1) * NLAT];
        float f2 = fp[(j + 2) * NLAT];
        float f3 = fp[(j + 3) * NLAT];
        a0 = fmaf(f0, ctab[idx], a0);
        a1 = fmaf(f1, ctab[(idx + m) & 255], a1);
        a2 = fmaf(f2, ctab[(idx + m2) & 255], a2);
        a3 = fmaf(f3, ctab[(idx + m3) & 255], a3);
        idx = (idx + m4) & 255;
    }
    fre[t] = ((a0 + a1) + (a2 + a3)) * (2.0f * PI_F / (float)NLON);
    __syncthreads();

    // phase 2: coeff[l] = sum_k fre[k] * W[k][l], split over 2 k-halves
    int g = t >> 6, l = t & 63;
    if (l < LMAX) {
        float p0 = 0.f, p1 = 0.f;
        int k0 = g * 64;
        #pragma unroll 8
        for (int k = k0; k < k0 + 64; k += 2) {
            p0 = fmaf(fre[k],     sW[k * LMAX + l],       p0);
            p1 = fmaf(fre[k + 1], sW[(k + 1) * LMAX + l], p1);
        }
        ps[g][l] = p0 + p1;
    }
    __syncthreads();
    if (t < LMAX)
        out[(b * LMAX + t) * MMAX + m] = ps[0][t] + ps[1][t];
}

// ---------------------------------------------------------------------------
extern "C" void kernel_launch(void* const* d_in, const int* in_sizes, int n_in,
                              void* d_out, int out_size) {
    const float* tgt = (const float*)d_in[0];
    float* out = (float*)d_out;

    k_init<<<16 + MMAX, 256>>>(tgt);
    k_nn<<<dim3(MGRID / 512, BATCH), 512>>>();
    k_sht<<<dim3(MMAX, BATCH), 128>>>(out);
}